// round 12
// baseline (speedup 1.0000x reference)
#include <cuda_runtime.h>
#include <math.h>
#include <stdint.h>

// ===========================================================================
// StreamingSSMCell (B=8192, D=1024, DCONV=4) — tf32 GEMM + fused epilogue v2
//   G1: 256-thread CTAs, 128x128 interleaved tile (64 d's), 2 CTAs/SM so the
//       MUFU/streaming epilogue of one CTA overlaps the other CTA's MMAs.
//   G2: proven 512-thread tf32 ldmatrix kernel (unchanged from R11).
//   d_out layout: [ out (B*D) | h_new (B*D) | new_buf (B*D*4) ]
// ===========================================================================

#define D_MODEL 1024
#define BATCH   8192

__device__ float g_g[(size_t)BATCH * D_MODEL];   // gated activation

// ------------------------------ PTX helpers --------------------------------
__device__ __forceinline__ uint32_t smem_u32(const void* p) {
    uint32_t a;
    asm("{ .reg .u64 t; cvta.to.shared.u64 t, %1; cvt.u32.u64 %0, t; }"
        : "=r"(a) : "l"(p));
    return a;
}

#define CP_ASYNC16(dst, src) \
    asm volatile("cp.async.cg.shared.global [%0], [%1], 16;" :: "r"(dst), "l"(src))
#define CP_ASYNC_COMMIT() asm volatile("cp.async.commit_group;" ::: "memory")
#define CP_ASYNC_WAIT1()  asm volatile("cp.async.wait_group 1;" ::: "memory")

__device__ __forceinline__ uint32_t rna(uint32_t x) {
    uint32_t r;
    asm("cvt.rna.tf32.f32 %0, %1;" : "=r"(r) : "f"(__uint_as_float(x)));
    return r;
}

#define LDSM_X4(r0, r1, r2, r3, addr)                                          \
    asm volatile("ldmatrix.sync.aligned.m8n8.x4.shared.b16 {%0,%1,%2,%3}, [%4];" \
        : "=r"(r0), "=r"(r1), "=r"(r2), "=r"(r3) : "r"(addr))

#define MMA_TF32(c, a, b)                                                      \
    asm volatile("mma.sync.aligned.m16n8k8.row.col.f32.tf32.tf32.f32 "         \
        "{%0,%1,%2,%3}, {%4,%5,%6,%7}, {%8,%9}, {%0,%1,%2,%3};"                \
        : "+f"((c)[0]), "+f"((c)[1]), "+f"((c)[2]), "+f"((c)[3])               \
        : "r"((a)[0]), "r"((a)[1]), "r"((a)[2]), "r"((a)[3]),                  \
          "r"((b)[0]), "r"((b)[1]))

__device__ __forceinline__ float silu_f(float x) {
    return __fdividef(x, 1.0f + __expf(-x));
}

// ====================== GEMM1 + fused elementwise (v2) ======================
// 256 threads, tile 128m x 128 interleaved cols (= 64 d's), 3-stage cp.async,
// 2 CTAs/SM. B tile row r <- W_in row (r&1)*D + n0d + (r>>1).
#define G1_ATILE   (128 * 80)             // 10240 B per operand tile
#define G1_STAGE   (2 * G1_ATILE)         // 20480 B
#define G1_NSTAGE  3
#define G1_SMEM    (G1_NSTAGE * G1_STAGE) // 61440 B

__global__ __launch_bounds__(256, 2)
void gemm1_fused(const float* __restrict__ A,        // x [B, D]
                 const float* __restrict__ Bm,       // W_in [2D, D]
                 const float* __restrict__ b_in,     // [2D]
                 const float* __restrict__ h,        // [B, D]
                 const float* __restrict__ conv_buf, // [B, D, 4]
                 const float* __restrict__ conv_w,   // [D, 4]
                 const float* __restrict__ conv_b,   // [D]
                 float* __restrict__ out_hnew,       // [B, D]
                 float* __restrict__ out_newbuf,     // [B, D, 4]
                 float* __restrict__ g_out)          // [B, D]
{
    extern __shared__ float smem[];
    const uint32_t sbase = smem_u32(smem);
    const int tid  = threadIdx.x;
    const int lane = tid & 31;
    const int wid  = tid >> 5;
    const int wm = wid >> 2;            // 0..1
    const int wn = wid & 3;             // 0..3
    const int g  = lane >> 2;
    const int tg = lane & 3;
    const int m0  = blockIdx.y * 128;
    const int n0d = blockIdx.x * 64;    // 64 d's per tile (128 interleaved cols)
    const int T = D_MODEL / 16;

    uint32_t a_off[4];
    #pragma unroll
    for (int i = 0; i < 4; i++) {
        const int row = wm * 64 + i * 16 + (lane & 15);
        a_off[i] = (uint32_t)(row * 80 + ((lane >> 4) * 16));
    }
    uint32_t b_off[2];
    #pragma unroll
    for (int jj = 0; jj < 2; jj++) {
        const int row = wn * 32 + jj * 16 + ((lane >> 4) << 3) + (lane & 7);
        b_off[jj] = (uint32_t)(G1_ATILE + row * 80 + (((lane >> 3) & 1) * 16));
    }

    float acc[4][4][4];
    #pragma unroll
    for (int i = 0; i < 4; i++)
        #pragma unroll
        for (int j = 0; j < 4; j++)
            #pragma unroll
            for (int r = 0; r < 4; r++) acc[i][j][r] = 0.0f;

    #define TLOAD1(t) do {                                                     \
        const uint32_t _s = sbase + ((t) % G1_NSTAGE) * G1_STAGE;              \
        _Pragma("unroll")                                                      \
        for (int _q = 0; _q < 2; _q++) {                                       \
            const int _id = tid + _q * 256;                                    \
            const int _r = _id >> 2, _c = _id & 3;                             \
            CP_ASYNC16(_s + (uint32_t)(_r * 80 + _c * 16),                     \
                       A + (size_t)(m0 + _r) * D_MODEL + (size_t)(t) * 16 + _c * 4); \
        }                                                                      \
        _Pragma("unroll")                                                      \
        for (int _q = 0; _q < 2; _q++) {                                       \
            const int _id = tid + _q * 256;                                    \
            const int _r = _id >> 2, _c = _id & 3;                             \
            const int _grow = ((_r & 1) ? D_MODEL : 0) + n0d + (_r >> 1);      \
            CP_ASYNC16(_s + (uint32_t)(G1_ATILE + _r * 80 + _c * 16),          \
                       Bm + (size_t)_grow * D_MODEL + (size_t)(t) * 16 + _c * 4); \
        }                                                                      \
        CP_ASYNC_COMMIT();                                                     \
    } while (0)

    TLOAD1(0);
    TLOAD1(1);

    for (int t = 0; t < T; t++) {
        CP_ASYNC_WAIT1();
        __syncthreads();

        if (t + 2 < T) { TLOAD1(t + 2); } else { CP_ASYNC_COMMIT(); }

        const uint32_t st = sbase + (t % G1_NSTAGE) * G1_STAGE;

        #pragma unroll
        for (int ks = 0; ks < 2; ks++) {
            const uint32_t kb = (uint32_t)(ks * 32);
            uint32_t af[4][4], bf[4][2];
            #pragma unroll
            for (int i = 0; i < 4; i++)
                LDSM_X4(af[i][0], af[i][1], af[i][2], af[i][3],
                        st + a_off[i] + kb);
            #pragma unroll
            for (int jj = 0; jj < 2; jj++)
                LDSM_X4(bf[2 * jj][0], bf[2 * jj][1],
                        bf[2 * jj + 1][0], bf[2 * jj + 1][1],
                        st + b_off[jj] + kb);
            #pragma unroll
            for (int i = 0; i < 4; i++)
                #pragma unroll
                for (int q = 0; q < 4; q++) af[i][q] = rna(af[i][q]);
            #pragma unroll
            for (int j = 0; j < 4; j++) {
                bf[j][0] = rna(bf[j][0]);
                bf[j][1] = rna(bf[j][1]);
            }
            #pragma unroll
            for (int i = 0; i < 4; i++)
                #pragma unroll
                for (int j = 0; j < 4; j++)
                    MMA_TF32(acc[i][j], af[i], bf[j]);
        }
    }
    #undef TLOAD1

    // ---------------- fused elementwise epilogue ----------------
    // fragment (i,j): cols (even,odd) = (x_inner, z) for d = n0d + wn*16+j*4+tg
    #pragma unroll
    for (int j = 0; j < 4; j++) {
        const int d = n0d + wn * 16 + j * 4 + tg;
        const float bi  = b_in[d];
        const float biz = b_in[D_MODEL + d];
        const float4 cw = *(const float4*)(conv_w + (size_t)d * 4);
        const float cbv = conv_b[d];
        const float tt = 2.302585092994046f
                       + (float)d * (7.600902459542082f - 2.302585092994046f)
                         / (float)(D_MODEL - 1);
        const float dec = __expf(-__expf(-tt));

        #pragma unroll
        for (int i = 0; i < 4; i++) {
            #pragma unroll
            for (int e = 0; e < 2; e++) {
                const int row = m0 + wm * 64 + i * 16 + g + e * 8;
                const size_t idx = (size_t)row * D_MODEL + d;

                const float xi = acc[i][j][e * 2 + 0] + bi;
                const float zz = acc[i][j][e * 2 + 1] + biz;

                const float4 cb = *(const float4*)(conv_buf + idx * 4);
                float co = cb.y * cw.x + cb.z * cw.y + cb.w * cw.z
                         + xi * cw.w + cbv;
                co = silu_f(co);

                const float hn = dec * h[idx] + (1.0f - dec) * co;

                out_hnew[idx] = hn;
                float4 nb; nb.x = cb.y; nb.y = cb.z; nb.z = cb.w; nb.w = xi;
                *(float4*)(out_newbuf + idx * 4) = nb;
                g_out[idx] = hn * silu_f(zz);
            }
        }
    }
}

// ========================= GEMM2 (proven tf32, unchanged) ===================
#define BM 128
#define BN 256
#define BK 32
#define KPAD 36
#define NTHREADS 512
#define NSTAGE 3
#define A_TILE_WORDS (BM * KPAD)
#define B_TILE_WORDS (BN * KPAD)
#define STAGE_WORDS  (A_TILE_WORDS + B_TILE_WORDS)
#define SMEM_BYTES   (NSTAGE * STAGE_WORDS * 4)

__global__ __launch_bounds__(NTHREADS, 1)
void gemm_tf32(const float* __restrict__ A, int lda,
               const float* __restrict__ Bm, int ldb,
               const float* __restrict__ bias,
               float* __restrict__ C, int ldc, int K)
{
    extern __shared__ float smem[];
    const uint32_t sbase = smem_u32(smem);
    const int tid  = threadIdx.x;
    const int lane = tid & 31;
    const int wid  = tid >> 5;
    const int wm = wid >> 3;
    const int wn = wid & 7;
    const int g  = lane >> 2;
    const int tg = lane & 3;
    const int m0 = blockIdx.y * BM;
    const int n0 = blockIdx.x * BN;

    const float* gA = A  + (size_t)m0 * lda;
    const float* gB = Bm + (size_t)n0 * ldb;

    uint32_t a_off[4];
    #pragma unroll
    for (int i = 0; i < 4; i++) {
        const int row = wm * 64 + i * 16 + (lane & 15);
        a_off[i] = (uint32_t)(row * KPAD + ((lane >> 4) << 2)) * 4u;
    }
    uint32_t b_off[2];
    #pragma unroll
    for (int jj = 0; jj < 2; jj++) {
        const int row = wn * 32 + jj * 16 + ((lane >> 4) << 3) + (lane & 7);
        b_off[jj] = (uint32_t)(row * KPAD + (((lane >> 3) & 1) << 2)) * 4u
                    + (uint32_t)(A_TILE_WORDS * 4);
    }

    float acc[4][4][4];
    #pragma unroll
    for (int i = 0; i < 4; i++)
        #pragma unroll
        for (int j = 0; j < 4; j++)
            #pragma unroll
            for (int r = 0; r < 4; r++) acc[i][j][r] = 0.0f;

    const int T = K / BK;

    #define LOAD_STAGE(t) do {                                                 \
        const uint32_t _s = sbase + ((t) % NSTAGE) * (STAGE_WORDS * 4);        \
        _Pragma("unroll")                                                      \
        for (int _q = 0; _q < 2; _q++) {                                       \
            const int _id = tid + _q * NTHREADS;                               \
            const int _r = _id >> 3, _c = _id & 7;                             \
            CP_ASYNC16(_s + _r * (KPAD * 4) + _c * 16,                         \
                       gA + (size_t)_r * lda + (size_t)(t) * BK + _c * 4);     \
        }                                                                      \
        const uint32_t _sb = _s + A_TILE_WORDS * 4;                            \
        _Pragma("unroll")                                                      \
        for (int _q = 0; _q < 4; _q++) {                                       \
            const int _id = tid + _q * NTHREADS;                               \
            const int _r = _id >> 3, _c = _id & 7;                             \
            CP_ASYNC16(_sb + _r * (KPAD * 4) + _c * 16,                        \
                       gB + (size_t)_r * ldb + (size_t)(t) * BK + _c * 4);     \
        }                                                                      \
        CP_ASYNC_COMMIT();                                                     \
    } while (0)

    LOAD_STAGE(0);
    LOAD_STAGE(1);

    for (int t = 0; t < T; t++) {
        CP_ASYNC_WAIT1();
        __syncthreads();

        if (t + 2 < T) { LOAD_STAGE(t + 2); } else { CP_ASYNC_COMMIT(); }

        const uint32_t st = sbase + (t % NSTAGE) * (STAGE_WORDS * 4);

        #pragma unroll
        for (int k0 = 0; k0 < BK; k0 += 8) {
            const uint32_t kb = (uint32_t)(k0 * 4);
            uint32_t af[4][4], bf[4][2];
            #pragma unroll
            for (int i = 0; i < 4; i++)
                LDSM_X4(af[i][0], af[i][1], af[i][2], af[i][3],
                        st + a_off[i] + kb);
            #pragma unroll
            for (int jj = 0; jj < 2; jj++)
                LDSM_X4(bf[jj * 2][0], bf[jj * 2][1],
                        bf[jj * 2 + 1][0], bf[jj * 2 + 1][1],
                        st + b_off[jj] + kb);
            #pragma unroll
            for (int i = 0; i < 4; i++)
                #pragma unroll
                for (int q = 0; q < 4; q++) af[i][q] = rna(af[i][q]);
            #pragma unroll
            for (int j = 0; j < 4; j++) {
                bf[j][0] = rna(bf[j][0]);
                bf[j][1] = rna(bf[j][1]);
            }
            #pragma unroll
            for (int i = 0; i < 4; i++)
                #pragma unroll
                for (int j = 0; j < 4; j++)
                    MMA_TF32(acc[i][j], af[i], bf[j]);
        }
    }
    #undef LOAD_STAGE

    #pragma unroll
    for (int j = 0; j < 4; j++) {
        const int col = n0 + wn * 32 + j * 8 + tg * 2;
        const float2 bb = *(const float2*)(bias + col);
        #pragma unroll
        for (int i = 0; i < 4; i++) {
            const int r0 = m0 + wm * 64 + i * 16 + g;
            float2 v0; v0.x = acc[i][j][0] + bb.x; v0.y = acc[i][j][1] + bb.y;
            *(float2*)(C + (size_t)r0 * ldc + col) = v0;
            float2 v1; v1.x = acc[i][j][2] + bb.x; v1.y = acc[i][j][3] + bb.y;
            *(float2*)(C + (size_t)(r0 + 8) * ldc + col) = v1;
        }
    }
}

// ------------------------------- launch ------------------------------------
extern "C" void kernel_launch(void* const* d_in, const int* in_sizes, int n_in,
                              void* d_out, int out_size)
{
    const float* x        = (const float*)d_in[0];
    const float* h        = (const float*)d_in[1];
    const float* conv_buf = (const float*)d_in[2];
    const float* W_in     = (const float*)d_in[3];
    const float* b_in     = (const float*)d_in[4];
    const float* conv_w   = (const float*)d_in[5];
    const float* conv_b   = (const float*)d_in[6];
    const float* W_out    = (const float*)d_in[7];
    const float* b_out    = (const float*)d_in[8];

    const int D = in_sizes[6];
    const int B = in_sizes[0] / D;

    float* out      = (float*)d_out;
    float* out_hnew = out + (size_t)B * D;
    float* out_nbuf = out + (size_t)2 * B * D;

    cudaFuncSetAttribute(gemm1_fused,
                         cudaFuncAttributeMaxDynamicSharedMemorySize, G1_SMEM);
    cudaFuncSetAttribute(gemm_tf32,
                         cudaFuncAttributeMaxDynamicSharedMemorySize, SMEM_BYTES);

    // GEMM1 + fused elementwise: writes h_new, new_buf, g (2 CTAs/SM)
    {
        dim3 grid(D / 64, B / 128);     // (16, 64) = 1024 CTAs
        gemm1_fused<<<grid, 256, G1_SMEM>>>(
            x, W_in, b_in, h, conv_buf, conv_w, conv_b,
            out_hnew, out_nbuf, g_g);
    }

    // GEMM2: out = g @ W_out^T + b_out  [B, D]
    {
        dim3 grid(D / BN, B / BM);      // (4, 64)
        gemm_tf32<<<grid, NTHREADS, SMEM_BYTES>>>(g_g, D, W_out, D, b_out,
                                                  out, D, D);
    }
}